// round 12
// baseline (speedup 1.0000x reference)
#include <cuda_runtime.h>
#include <math.h>
#include <stdint.h>

#define MM    4095
#define T     9
#define NT    455            // 9 * 455 = 4095
#define NTILE 227            // off-diag tiles per sigma
#define FPAD  228            // padded cell-row length (float2), 228*8 = 1824 (16B mult)
#define INV2  228            // 2*228 == 1 (mod 455)
#define CELLS 81             // T*T
#define HCELL 45             // T*(T+1)/2 : first late-half cell index
#define CPT   4              // columns per CTA (2 per thread, f32x2-packed)
#define THREADS 454          // 227 slots * 2 threads
#define DPAD  82             // padded diag-tile length (float2), 82*8 = 656 (16B mult)
#define CHUNK 11
#define NPAIRS (4095LL*2048LL)

typedef unsigned long long u64_t;

// Off-diag rotations: [sigma][cell][m-1] (rows padded to FPAD float2)
__device__ __align__(16) float2 g_csF[(size_t)NT * CELLS * FPAD];   // ~67 MB
// Diagonal-tile rotations: [A][ia*T+ib] (specials at ia==ib), padded rows
__device__ __align__(16) float2 g_csD[NT * DPAD];

__host__ __device__ __forceinline__ constexpr int cell_of(int d, int p) {
    return (d < T) ? d * (d + 1) / 2 + p
                   : HCELL + (d - T) * (3 * T - 1 - d) / 2 + (p - (d - (T - 1)));
}

__global__ void precompute(const float* __restrict__ thetas,
                           const int*   __restrict__ round_theta) {
    long long idx = blockIdx.x * (long long)blockDim.x + threadIdx.x;
    if (idx >= NPAIRS) return;
    int r = (int)(idx >> 11), k = (int)(idx & 2047);
    float th = thetas[round_theta[idx]];
    float s, c; sincosf(th, &s, &c);
    if (k == 0) {                         // special: rows (r, 4095), i = r
        int u = (int)((2048LL * r) % MM);
        int A = u / T, ia = u % T;
        g_csD[A * DPAD + ia * T + ia] = make_float2(c, s);
    } else {
        int a0 = r + k; if (a0 >= MM) a0 -= MM;
        int b0 = r - k; if (b0 < 0)   b0 += MM;
        int i = min(a0, b0), j = max(a0, b0);
        int ui = (int)((2048LL * i) % MM);
        int uj = (int)((2048LL * j) % MM);
        int ua = min(ui, uj), ub = max(ui, uj);
        float sg = (ua == ui) ? s : -s;   // orient for (x = ua-row, y = ub-row)
        int A = ua / T, ia = ua % T;
        int B = ub / T, ib = ub % T;
        if (A == B) {
            g_csD[A * DPAD + ia * T + ib] = make_float2(c, sg);
        } else {
            int d   = ia + ib;
            int sig = A + B; if (sig >= NT) sig -= NT;
            int aD  = (sig * INV2) % NT;
            int mm  = A - aD; if (mm < 0) mm += NT;
            int m   = (mm <= NTILE) ? mm : NT - mm;
            g_csF[((size_t)sig * CELLS + cell_of(d, ia)) * FPAD + (m - 1)]
                = make_float2(c, sg);
        }
    }
}

// Packed Givens rotation on 2 columns: per lane, bit-identical to
// x' = fmaf(c, x, -(s*y)); y' = fmaf(s, x, c*y).
__device__ __forceinline__ void rot2(u64_t& x, u64_t& y, float2 cs) {
    unsigned ci = __float_as_uint(cs.x);
    unsigned si = __float_as_uint(cs.y);
    u64_t c2, s2, t, xo = x;
    asm("mov.b64 %0, {%1, %1};" : "=l"(c2) : "r"(ci));
    asm("mov.b64 %0, {%1, %1};" : "=l"(s2) : "r"(si));
    asm("mul.rn.f32x2 %0, %1, %2;" : "=l"(t) : "l"(s2), "l"(y));
    t ^= 0x8000000080000000ULL;                      // exact negation
    asm("fma.rn.f32x2 %0, %1, %2, %3;" : "=l"(x) : "l"(c2), "l"(xo), "l"(t));
    asm("mul.rn.f32x2 %0, %1, %2;" : "=l"(t) : "l"(c2), "l"(y));
    asm("fma.rn.f32x2 %0, %1, %2, %3;" : "=l"(y) : "l"(s2), "l"(xo), "l"(t));
}

__device__ __forceinline__ void tileAB(int sigma, int m, int& A, int& B) {
    int aD = (sigma * INV2) % NT;
    int a = aD + m; if (a >= NT) a -= NT;
    int b = aD - m; if (b < 0)   b += NT;
    A = min(a, b); B = max(a, b);
}

__device__ __forceinline__ void cpasync16(float* sdst, const char* gsrc) {
    uint32_t sa = (uint32_t)__cvta_generic_to_shared(sdst);
    asm volatile("cp.async.cg.shared.global [%0], [%1], 16;\n" :: "r"(sa), "l"(gsrc));
}
__device__ __forceinline__ void cp_commit() { asm volatile("cp.async.commit_group;\n"); }
__device__ __forceinline__ void cp_wait0()  { asm volatile("cp.async.wait_group 0;\n" ::: "memory"); }

// Stage cells [C0,C1) of sigma into smem buffer. 114 16B-units per cell.
__device__ __forceinline__ void stage(int sig, int C0, int C1, float* buf, int tid) {
    const char* g = (const char*)(g_csF + ((size_t)sig * CELLS + C0) * FPAD);
    const int n16 = (C1 - C0) * (FPAD * 8 / 16);
    for (int u = tid; u < n16; u += THREADS)
        cpasync16(buf + u * 4, g + (size_t)u * 16);
}
// Stage the two diag tiles (aE: 2aE==s, aL: 2aL==s-1) for step s.
__device__ __forceinline__ void stage_diag(int s, float* bufD, int tid) {
    int aE = (s * INV2) % NT;
    int aL = aE - INV2; if (aL < 0) aL += NT;
    const char* gE = (const char*)(g_csD + aE * DPAD);
    const char* gL = (const char*)(g_csD + aL * DPAD);
    if (tid < 41) {                     // 41*16 = 656 = DPAD*8
        cpasync16(bufD + tid * 4, gE + tid * 16);
        cpasync16(bufD + DPAD * 2 + tid * 4, gL + tid * 16);
    }
}

// Apply cells [C0,C1) from buffer whose first cell is CS. bufm = buf + (m-1).
template<int CS, int C0, int C1>
__device__ __forceinline__ void chunk_visit(const float2* __restrict__ bufm,
                                            u64_t (&ra)[T], u64_t (&rb)[T]) {
    #pragma unroll
    for (int d = 0; d < 2 * T - 1; ++d) {
        const int plo = (d < T) ? 0 : d - (T - 1);
        const int phi = (d < T) ? d : (T - 1);
        #pragma unroll
        for (int p = plo; p <= phi; ++p) {
            const int cell = cell_of(d, p);
            if (cell >= C0 && cell < C1)
                rot2(ra[p], rb[d - p], bufm[(cell - CS) * FPAD]);
        }
    }
}

// Diagonal phase for step s (2 threads, 2 packed cols each): early half of
// tile aE (2aE==s), late half of tile aL (2aL==s-1), specials chained through
// row 4095 in exact round order.
__device__ __forceinline__ void visit_diag(float* __restrict__ sm_,
                                           const float2* __restrict__ dbuf,
                                           int s, int cc) {
    int aE = (s * INV2) % NT;
    int aL = aE - INV2; if (aL < 0) aL += NT;
    const float2* csE = dbuf;
    const float2* csL = dbuf + DPAD;
    u64_t re[T], rl[T];
    float* pe = sm_ + (T * CPT) * aE + 2 * cc;
    float* pl = sm_ + (T * CPT) * aL + 2 * cc;
    u64_t sp = *(u64_t*)(sm_ + MM * CPT + 2 * cc);
    #pragma unroll
    for (int q = 0; q < T; ++q) { re[q] = *(u64_t*)(pe + q * CPT);
                                  rl[q] = *(u64_t*)(pl + q * CPT); }
    #pragma unroll
    for (int dp = 0; dp < T; ++dp) {                 // round T*s + dp
        #pragma unroll
        for (int p = 0; 2 * p < dp; ++p) rot2(re[p], re[dp - p], csE[p * T + (dp - p)]);
        if ((dp & 1) == 0) rot2(re[dp >> 1], sp, csE[(dp >> 1) * (T + 1)]);
        if (dp <= T - 2) {
            const int dd = dp + T;
            #pragma unroll
            for (int p = dp + 1; 2 * p < dd; ++p) rot2(rl[p], rl[dd - p], csL[p * T + (dd - p)]);
            if ((dd & 1) == 0) rot2(rl[dd >> 1], sp, csL[(dd >> 1) * (T + 1)]);
        }
    }
    #pragma unroll
    for (int q = 0; q < T; ++q) { *(u64_t*)(pe + q * CPT) = re[q];
                                  *(u64_t*)(pl + q * CPT) = rl[q]; }
    *(u64_t*)(sm_ + MM * CPT + 2 * cc) = sp;
}

__device__ __forceinline__ void loadT(u64_t (&r)[T], const float* p) {
    #pragma unroll
    for (int q = 0; q < T; ++q) r[q] = *(const u64_t*)(p + q * CPT);
}
__device__ __forceinline__ void storeT(const u64_t (&r)[T], float* p) {
    #pragma unroll
    for (int q = 0; q < T; ++q) *(u64_t*)(p + q * CPT) = r[q];
}

#define SLAB_F 16384                       // 4096 rows * stride 4
#define DBUF_F (2 * DPAD * 2)              // 328 floats
#define CBUF_F (CHUNK * FPAD * 2)          // 5016 floats per buffer
#define SMEM_F (SLAB_F + DBUF_F + 2 * CBUF_F)   // 26744 floats = 106976 B

// Pipeline: wait current chunk, barrier, issue next stage, compute.
// Buffer parity fixed by chunk index CS/CHUNK.
#define PIPE(CS, C0, C1, STAGE_STMT) do {                                      \
    cp_wait0(); __syncthreads();                                               \
    { STAGE_STMT; } cp_commit();                                               \
    const float2* bm_ = (const float2*)((((CS) / CHUNK) & 1) ? buf1 : buf0)    \
                        + (m - 1);                                             \
    chunk_visit<CS, C0, C1>(bm_, ra, rb);                                      \
} while (0)

__global__ void __launch_bounds__(THREADS, 2)
rotmat_kernel(float* __restrict__ out) {
    extern __shared__ float sm[];          // slab | bufD | buf0 | buf1
    float* bufD = sm + SLAB_F;
    float* buf0 = bufD + DBUF_F;
    float* buf1 = buf0 + CBUF_F;
    const int c0  = blockIdx.x * CPT;
    const int tid = threadIdx.x;
    const int slot = tid >> 1;             // 0..226
    const int cc   = tid & 1;              // packed column pair within slot
    const int m    = slot + 1;             // tile index 1..227

    for (int i = tid; i < SLAB_F; i += THREADS) sm[i] = 0.0f;
    __syncthreads();
    if (tid < CPT) {                       // identity in u-coordinates
        int c = c0 + tid;
        int u = (c == MM) ? MM : (int)((2048LL * c) % MM);
        sm[u * CPT + tid] = 1.0f;
    }
    __syncthreads();

    u64_t ra[T], rb[T];
    int A, B;

    // ---- Prologue: late half (cells 45..80) of sigma = 454 ----
    stage(NT - 1, 44, 55, buf0, tid); stage_diag(0, bufD, tid); cp_commit();
    tileAB(NT - 1, m, A, B);
    float* pa = sm + (T * CPT) * A + 2 * cc;
    float* pb = sm + (T * CPT) * B + 2 * cc;
    PIPE(44, 45, 55, { stage(NT - 1, 55, 66, buf1, tid);
                       loadT(ra, pa); loadT(rb, pb); });
    PIPE(55, 55, 66, stage(NT - 1, 66, 77, buf0, tid));
    PIPE(66, 66, 77, stage(NT - 1, 77, 81, buf1, tid));
    PIPE(77, 77, 81, stage(0, 0, 11, buf0, tid));
    storeT(ra, pa); storeT(rb, pb);
    __syncthreads();
    // invariant at loop top: chunk (s,[0,11)) in flight -> buf0; diag(s) in bufD

    for (int s = 0; s < NT - 1; ++s) {
        if (tid < 2) visit_diag(sm, (const float2*)bufD, s, tid);
        tileAB(s, m, A, B);
        pa = sm + (T * CPT) * A + 2 * cc;
        pb = sm + (T * CPT) * B + 2 * cc;
        PIPE(0, 0, 11,   { stage(s, 11, 22, buf1, tid); stage_diag(s + 1, bufD, tid);
                           loadT(ra, pa); loadT(rb, pb); });
        PIPE(11, 11, 22,  stage(s, 22, 33, buf0, tid));
        PIPE(22, 22, 33,  stage(s, 33, 44, buf1, tid));
        PIPE(33, 33, 44,  stage(s, 44, 55, buf0, tid));
        PIPE(44, 44, 55,  stage(s, 55, 66, buf1, tid));
        PIPE(55, 55, 66,  stage(s, 66, 77, buf0, tid));
        PIPE(66, 66, 77,  stage(s, 77, 81, buf1, tid));
        PIPE(77, 77, 81,  stage(s + 1, 0, 11, buf0, tid));
        storeT(ra, pa); storeT(rb, pb);
        __syncthreads();
    }

    // ---- Epilogue: s = 454, early half (cells 0..44) ----
    {
        const int s = NT - 1;
        if (tid < 2) visit_diag(sm, (const float2*)bufD, s, tid);
        tileAB(s, m, A, B);
        pa = sm + (T * CPT) * A + 2 * cc;
        pb = sm + (T * CPT) * B + 2 * cc;
        PIPE(0, 0, 11,   { stage(s, 11, 22, buf1, tid);
                           loadT(ra, pa); loadT(rb, pb); });
        PIPE(11, 11, 22,  stage(s, 22, 33, buf0, tid));
        PIPE(22, 22, 33,  stage(s, 33, 44, buf1, tid));
        PIPE(33, 33, 44,  stage(s, 44, 45, buf0, tid));
        PIPE(44, 44, 45,  { });
        storeT(ra, pa); storeT(rb, pb);
        __syncthreads();
    }

    // Writeback: slab u-row v -> absolute row x = 2v mod 4095 (4095 -> 4095)
    for (int v = tid; v < 4096; v += THREADS) {
        int x = (v == MM) ? MM : ((2 * v) % MM);
        float4 val = *(const float4*)(sm + v * CPT);
        *(float4*)(out + (size_t)x * 4096 + c0) = val;
    }
}

extern "C" void kernel_launch(void* const* d_in, const int* in_sizes, int n_in,
                              void* d_out, int out_size) {
    const float* thetas      = (const float*)d_in[0];
    const int*   round_theta = (const int*)d_in[3];
    float*       out         = (float*)d_out;
    (void)in_sizes; (void)n_in; (void)out_size;

    const int smem = SMEM_F * (int)sizeof(float);       // 106,976 B
    cudaFuncSetAttribute(rotmat_kernel,
                         cudaFuncAttributeMaxDynamicSharedMemorySize, smem);

    precompute<<<(int)((NPAIRS + 255) / 256), 256>>>(thetas, round_theta);

    rotmat_kernel<<<4096 / CPT, THREADS, smem>>>(out);
}